// round 16
// baseline (speedup 1.0000x reference)
#include <cuda_runtime.h>

// LSTM: B=2048, T=512, I=1, H=64, gates=256 (i,f,g,o), O=1. fp32 throughout.
// Grid: 296 CTAs x 256 threads = 2 CTAs/SM (one balanced wave), 512 thr/SM
// -> 4 warps/SMSP for latency hiding at the SAME fma floor as R14.
// Each CTA owns RPB=7 batch rows for the full T=512 recurrence.
//
// ONE GATE ROW PER THREAD (halves weight regs vs R14): warp w covers cells
// m in [8w, 8w+8). Lane l: q = l>>3 selects gate (0:i 1:f 2:g 3:o), cell
// m = 8w + (l&7), gate row j = m + 64q. All 4 gates of a cell sit in one
// warp -> cell update via 3x shfl.xor(8/16/24). h double-buffered in SMEM,
// ONE __syncthreads per step. Weights f32x2-packed in regs (32 u64 = 64
// regs). Activations: single MUFU.TANH, sigmoid 1/2 pre-folded into weights
// (R14 win). Step body: ALL dots first (R14 ordering - R15's staggered
// epilogue regressed due to in-order issue), then all epilogues.

#define BATCH  2048
#define TSTEPS 512
#define HID    64
#define RPB    7
#define NTHR   256
#define GRID   296   // 2 x 148 SMs; 296*7 = 2072 >= 2048 (tail clamped)

typedef unsigned long long u64;

__device__ __forceinline__ void fma2(u64 &acc, u64 a, u64 b) {
    asm("fma.rn.f32x2 %0, %1, %2, %0;" : "+l"(acc) : "l"(a), "l"(b));
}

__device__ __forceinline__ float2 unpack2(u64 v) {
    float2 r;
    asm("mov.b64 {%0, %1}, %2;" : "=f"(r.x), "=f"(r.y) : "l"(v));
    return r;
}

__device__ __forceinline__ u64 pack2(float lo, float hi) {
    u64 v;
    asm("mov.b64 %0, {%1, %2};" : "=l"(v) : "f"(lo), "f"(hi));
    return v;
}

// Hardware tanh (MUFU.TANH, sm_75+). Single op, lat ~16, abs err ~2^-11.
__device__ __forceinline__ float tanh_hw(float x) {
    float r;
    asm("tanh.approx.f32 %0, %1;" : "=f"(r) : "f"(x));
    return r;
}

// Scale both packed floats of a u64 by s.
__device__ __forceinline__ u64 scale2(u64 v, float s) {
    float2 p = unpack2(v);
    return pack2(p.x * s, p.y * s);
}

__global__ __launch_bounds__(NTHR, 2)
void lstm_fused_kernel(const float* __restrict__ x,      // [B, T, 1]
                       const float* __restrict__ w_ih,   // [256, 1]
                       const float* __restrict__ w_hh,   // [256, 64]
                       const float* __restrict__ b_ih,   // [256]
                       const float* __restrict__ b_hh,   // [256]
                       const float* __restrict__ w_lin,  // [1, 64]
                       const float* __restrict__ b_lin,  // [1]
                       float* __restrict__ out)          // [B, 1]
{
    __shared__ float sh_x[RPB * TSTEPS];      // 14 KB
    __shared__ float sh_h[2][RPB][HID];       // 3.5 KB, double-buffered

    const int t  = threadIdx.x;
    const int l  = t & 31;
    const int w  = t >> 5;                    // warp 0..7
    const int q  = l >> 3;                    // gate: 0=i 1=f 2=g 3=o
    const int m  = (w << 3) + (l & 7);        // cell 0..63
    const int j  = m + (q << 6);              // gate row 0..255
    const int b0 = blockIdx.x * RPB;

    // Sigmoid gates (i,f,o) get the 1/2 pre-folded into their weights;
    // g (q==2) is plain tanh.
    const float sc = (q == 2) ? 1.0f : 0.5f;
    const float Ac = (q == 2) ? 1.0f : 0.5f;  // act = Ac*tanh(pre) + Cc
    const float Cc = (q == 2) ? 0.0f : 0.5f;

    // ---- this gate row of W_hh into registers: 32 u64 = 64 regs ----
    u64 wj[HID / 2];
    {
        const u64* w64 = reinterpret_cast<const u64*>(w_hh) + (size_t)j * (HID / 2);
#pragma unroll
        for (int k = 0; k < HID / 2; ++k) wj[k] = scale2(w64[k], sc);
    }
    const float wihS  = sc * w_ih[j];
    const float biasS = sc * (b_ih[j] + b_hh[j]);

    // ---- stage x: 7 rows x 512 steps = 896 float4, clamp row for tail CTA ----
    {
        const float4* src = reinterpret_cast<const float4*>(x);
        float4* dst = reinterpret_cast<float4*>(sh_x);
#pragma unroll
        for (int i = 0; i < 4; ++i) {                  // 4*256=1024 >= 896
            int idx = t + i * NTHR;
            if (idx < RPB * TSTEPS / 4) {
                int rl = idx >> 7;                     // 128 float4 per row
                int g  = b0 + rl;
                if (g > BATCH - 1) g = BATCH - 1;      // clamp (unused rows)
                dst[idx] = src[(size_t)g * (TSTEPS / 4) + (idx & 127)];
            }
        }
    }
    // init h buffer 0 = 0
    for (int i = t; i < RPB * HID; i += NTHR)
        (&sh_h[0][0][0])[i] = 0.0f;

    float c[RPB];
#pragma unroll
    for (int r = 0; r < RPB; ++r) c[r] = 0.0f;

    __syncthreads();

    for (int step = 0; step < TSTEPS; ++step) {
        const int rb = step & 1;               // read buffer
        const int wb = rb ^ 1;                 // write buffer

        // ---------- dots for all 7 rows (r-outer, 2 chains per row) ----------
        float pre[RPB];
#pragma unroll
        for (int r = 0; r < RPB; ++r) {
            const ulonglong2* hp =
                reinterpret_cast<const ulonglong2*>(&sh_h[rb][r][0]);
            u64 a0 = 0ull, a1 = 0ull;
#pragma unroll
            for (int kk = 0; kk < HID / 4; ++kk) {    // 16 x LDS.128 broadcast
                ulonglong2 hv = hp[kk];
                fma2(a0, hv.x, wj[2 * kk]);
                fma2(a1, hv.y, wj[2 * kk + 1]);
            }
            float2 p0 = unpack2(a0), p1 = unpack2(a1);
            float xv = sh_x[r * TSTEPS + step];
            pre[r] = ((p0.x + p0.y) + (p1.x + p1.y)) + fmaf(xv, wihS, biasS);
        }

        // ---------- epilogues for all rows (7 independent chains) ----------
#pragma unroll
        for (int r = 0; r < RPB; ++r) {
            float act = fmaf(Ac, tanh_hw(pre[r]), Cc); // sig(i/f/o) or tanh(g)
            // owner lane (q==0, holds i): partners at l^8=f, l^16=g, l^24=o
            float fv = __shfl_xor_sync(0xFFFFFFFFu, act, 8);
            float gv = __shfl_xor_sync(0xFFFFFFFFu, act, 16);
            float ov = __shfl_xor_sync(0xFFFFFFFFu, act, 24);
            c[r] = fmaf(fv, c[r], act * gv);           // f*c + i*g (owner lanes)
            float hval = ov * tanh_hw(c[r]);
            if (q == 0) sh_h[wb][r][m] = hval;         // one owner per (r, m)
        }
        __syncthreads();
    }

    // ---------- output projection: out[b] = h_last . w_lin + b_lin ----------
    // Last write went to buffer wb = (511 & 1) ^ 1 = 0.
    if (t < RPB && (b0 + t) < BATCH) {
        float s = b_lin[0];
#pragma unroll
        for (int k = 0; k < HID; ++k)
            s = fmaf(sh_h[0][t][k], w_lin[k], s);
        out[b0 + t] = s;
    }
}

extern "C" void kernel_launch(void* const* d_in, const int* in_sizes, int n_in,
                              void* d_out, int out_size) {
    const float* x     = (const float*)d_in[0];
    const float* w_ih  = (const float*)d_in[1];
    const float* w_hh  = (const float*)d_in[2];
    const float* b_ih  = (const float*)d_in[3];
    const float* b_hh  = (const float*)d_in[4];
    const float* w_lin = (const float*)d_in[5];
    const float* b_lin = (const float*)d_in[6];
    float* out = (float*)d_out;

    lstm_fused_kernel<<<GRID, NTHR>>>(x, w_ih, w_hh, b_ih, b_hh,
                                      w_lin, b_lin, out);
}

// round 17
// speedup vs baseline: 1.4168x; 1.4168x over previous
#include <cuda_runtime.h>

// LSTM: B=2048, T=512, I=1, H=64, gates=256 (i,f,g,o), O=1. fp32 throughout.
// Grid: 296 CTAs x 128 threads = exactly 2 CTAs per SM (one balanced wave).
// Each CTA owns RPB=7 batch rows for the full T=512 recurrence.
//
// Body = Round-14 winner (754 us): cell-aligned gate ownership, warp w covers
// cells m in [16w, 16w+16); lane l<16 owns (i,g), lane l>=16 owns (f,o) of
// cell m. (f,o) reach the (i,g) lane via two shfl.xor(16). h double-buffered
// in SMEM -> ONE __syncthreads per step. W_hh in registers (f32x2-packed),
// dots via fma.rn.f32x2, 14 independent chains, kk-outer (R15 row-stagger
// regressed; R16 one-gate-per-thread saturated the LDS crossbar at L1=94.7%).
// Activations: single MUFU.TANH, sigmoid 1/2 pre-folded into weights.
//
// NEW this round: CTA PHASE STAGGER. The 2 warps on each SMSP come from the
// two co-resident CTAs (bid, bid+148 per the classic bid%148->SM map). R14's
// profile (2800 cyc/step = 1792 fma floor + ~1000 tail fully exposed) says
// they run phase-locked: both CTAs sit in the MUFU/shfl/BAR tail at once and
// the fma pipe drains. CTAs with bid>=148 therefore execute a one-time
// ~1400-cycle dependent-FFMA delay before the time loop, anti-phasing the
// pair so each CTA's tail overlaps the partner's FFMA2-dense dot region.

#define BATCH  2048
#define TSTEPS 512
#define HID    64
#define RPB    7
#define NTHR   128
#define GRID   296   // 2 x 148 SMs; 296*7 = 2072 >= 2048 (tail clamped)

typedef unsigned long long u64;

__device__ __forceinline__ void fma2(u64 &acc, u64 a, u64 b) {
    asm("fma.rn.f32x2 %0, %1, %2, %0;" : "+l"(acc) : "l"(a), "l"(b));
}

__device__ __forceinline__ float2 unpack2(u64 v) {
    float2 r;
    asm("mov.b64 {%0, %1}, %2;" : "=f"(r.x), "=f"(r.y) : "l"(v));
    return r;
}

__device__ __forceinline__ u64 pack2(float lo, float hi) {
    u64 v;
    asm("mov.b64 %0, {%1, %2};" : "=l"(v) : "f"(lo), "f"(hi));
    return v;
}

// Hardware tanh (MUFU.TANH, sm_75+). Single op, lat ~16, abs err ~2^-11.
__device__ __forceinline__ float tanh_hw(float x) {
    float r;
    asm("tanh.approx.f32 %0, %1;" : "=f"(r) : "f"(x));
    return r;
}

// Scale both packed floats of a u64 by s.
__device__ __forceinline__ u64 scale2(u64 v, float s) {
    float2 p = unpack2(v);
    return pack2(p.x * s, p.y * s);
}

__global__ __launch_bounds__(NTHR, 2)
void lstm_fused_kernel(const float* __restrict__ x,      // [B, T, 1]
                       const float* __restrict__ w_ih,   // [256, 1]
                       const float* __restrict__ w_hh,   // [256, 64]
                       const float* __restrict__ b_ih,   // [256]
                       const float* __restrict__ b_hh,   // [256]
                       const float* __restrict__ w_lin,  // [1, 64]
                       const float* __restrict__ b_lin,  // [1]
                       float* __restrict__ out)          // [B, 1]
{
    __shared__ float sh_x[RPB * TSTEPS];      // 14 KB
    __shared__ float sh_h[2][RPB][HID];       // 3.5 KB, double-buffered

    const int t  = threadIdx.x;
    const int l  = t & 31;
    const int w  = t >> 5;
    const int b0 = blockIdx.x * RPB;

    const int  m  = (w << 4) + (l & 15);      // cell this thread serves
    const bool hi = (l & 16) != 0;            // upper half-warp = (f,o) owner
    const int  jA = m + (hi ? 64 : 0);        // i-row (lo) / f-row (hi)
    const int  jB = jA + 128;                 // g-row (lo) / o-row (hi)

    // Gate A (i or f) is always sigmoid -> pre-scale weights by 0.5.
    // Gate B: g (lo) is tanh -> no scale; o (hi) is sigmoid -> 0.5.
    const float sB = hi ? 0.5f : 1.0f;

    // ---- W_hh rows into registers as k-pairs (64 x u64 = 128 regs) ----
    u64 wA[HID / 2], wB[HID / 2];
    {
        const u64* w64 = reinterpret_cast<const u64*>(w_hh);
        const u64* pa = w64 + (size_t)jA * (HID / 2);
        const u64* pb = w64 + (size_t)jB * (HID / 2);
#pragma unroll
        for (int k = 0; k < HID / 2; ++k) {
            wA[k] = scale2(pa[k], 0.5f);
            wB[k] = scale2(pb[k], sB);
        }
    }

    const float wihA  = 0.5f * w_ih[jA];
    const float wihB  = sB   * w_ih[jB];
    const float biasA = 0.5f * (b_ih[jA] + b_hh[jA]);
    const float biasB = sB   * (b_ih[jB] + b_hh[jB]);

    // Branchless post-tanh affine: act = Ac * tanh(pre) + Cc
    const float AcB = hi ? 0.5f : 1.0f;
    const float CcB = hi ? 0.5f : 0.0f;

    // ---- stage x: 7 rows x 512 steps = 896 float4, clamp row for tail CTA ----
    {
        const float4* src = reinterpret_cast<const float4*>(x);
        float4* dst = reinterpret_cast<float4*>(sh_x);
#pragma unroll
        for (int i = 0; i < (RPB * TSTEPS / 4) / NTHR; ++i) {   // 7 iters
            int idx = t + i * NTHR;            // [0, 896)
            int rl  = idx >> 7;                // 128 float4 per row
            int g   = b0 + rl;
            if (g > BATCH - 1) g = BATCH - 1;  // clamp (garbage rows unused)
            dst[idx] = src[(size_t)g * (TSTEPS / 4) + (idx & 127)];
        }
    }
    // init h buffer 0 = 0
#pragma unroll
    for (int i = t; i < RPB * HID; i += NTHR)
        (&sh_h[0][0][0])[i] = 0.0f;

    float c[RPB];
#pragma unroll
    for (int r = 0; r < RPB; ++r) c[r] = 0.0f;

    __syncthreads();

    // ---- phase stagger: anti-phase the co-resident CTA pair (bid, bid+148).
    // ~350 dependent FFMAs ~= 1400 cycles, about half of R14's step period.
    // Consumed by an empty asm so it cannot be dead-code-eliminated; has no
    // effect on results.
    if (blockIdx.x >= 148) {
        float d = biasA;
#pragma unroll
        for (int i = 0; i < 350; ++i)
            d = fmaf(d, 0.9999999f, 1e-30f);
        asm volatile("" :: "f"(d));
    }

    for (int step = 0; step < TSTEPS; ++step) {
        const int rb = step & 1;               // read buffer
        const int wb = rb ^ 1;                 // write buffer

        // ---------- gate pre-activations: f32x2 dot over k, 14 chains ----------
        u64 aA[RPB], aB[RPB];
#pragma unroll
        for (int r = 0; r < RPB; ++r) { aA[r] = 0ull; aB[r] = 0ull; }

#pragma unroll
        for (int kk = 0; kk < HID / 4; ++kk) {  // 16 iters, LDS.128 broadcast
            ulonglong2 hv[RPB];
#pragma unroll
            for (int r = 0; r < RPB; ++r)
                hv[r] = *(reinterpret_cast<const ulonglong2*>(&sh_h[rb][r][0]) + kk);
#pragma unroll
            for (int r = 0; r < RPB; ++r) {
                fma2(aA[r], hv[r].x, wA[2 * kk]);
                fma2(aA[r], hv[r].y, wA[2 * kk + 1]);
                fma2(aB[r], hv[r].x, wB[2 * kk]);
                fma2(aB[r], hv[r].y, wB[2 * kk + 1]);
            }
        }

        // ---------- activations: 1 MUFU.TANH each (+1 FFMA for sigmoids) ----------
        float actA[RPB], actB[RPB];
#pragma unroll
        for (int r = 0; r < RPB; ++r) {
            float xv = sh_x[r * TSTEPS + step];
            float2 pa = unpack2(aA[r]);
            float2 pb = unpack2(aB[r]);
            float preA = (pa.x + pa.y) + fmaf(xv, wihA, biasA);  // already /2
            float preB = (pb.x + pb.y) + fmaf(xv, wihB, biasB);
            actA[r] = fmaf(0.5f, tanh_hw(preA), 0.5f);           // sigmoid(i/f)
            actB[r] = fmaf(AcB, tanh_hw(preB), CcB);             // tanh(g)/sig(o)
        }

        // ---------- exchange (f,o) via shfl, update c/h, store h ----------
#pragma unroll
        for (int r = 0; r < RPB; ++r) {
            float fv = __shfl_xor_sync(0xFFFFFFFFu, actA[r], 16);  // f for lo
            float ov = __shfl_xor_sync(0xFFFFFFFFu, actB[r], 16);  // o for lo
            c[r] = fmaf(fv, c[r], actA[r] * actB[r]);  // f*c + i*g (lo lanes)
            float hval = ov * tanh_hw(c[r]);
            if (!hi) sh_h[wb][r][m] = hval;            // one owner per (r, m)
        }
        __syncthreads();
    }

    // ---------- output projection: out[b] = h_last . w_lin + b_lin ----------
    // Last write went to buffer wb = (511 & 1) ^ 1 = 0.
    if (t < RPB && (b0 + t) < BATCH) {
        float s = b_lin[0];
#pragma unroll
        for (int k = 0; k < HID; ++k)
            s = fmaf(sh_h[0][t][k], w_lin[k], s);
        out[b0 + t] = s;
    }
}

extern "C" void kernel_launch(void* const* d_in, const int* in_sizes, int n_in,
                              void* d_out, int out_size) {
    const float* x     = (const float*)d_in[0];
    const float* w_ih  = (const float*)d_in[1];
    const float* w_hh  = (const float*)d_in[2];
    const float* b_ih  = (const float*)d_in[3];
    const float* b_hh  = (const float*)d_in[4];
    const float* w_lin = (const float*)d_in[5];
    const float* b_lin = (const float*)d_in[6];
    float* out = (float*)d_out;

    lstm_fused_kernel<<<GRID, NTHR>>>(x, w_ih, w_hh, b_ih, b_hh,
                                      w_lin, b_lin, out);
}